// round 4
// baseline (speedup 1.0000x reference)
#include <cuda_runtime.h>
#include <cuda_bf16.h>
#include <float.h>

#define MAX_N 8192
#define BLOCK 256
#define ROWS_PER_BLOCK 8   // one row per warp
#define GRID (MAX_N / ROWS_PER_BLOCK)   // 1024

__device__ float        g_block_sum[GRID];
__device__ unsigned int g_done_count = 0;   // self-resets via atomicInc wrap

__global__ __launch_bounds__(BLOCK)
void triplet_fused_kernel(const float* __restrict__ sim,
                          const int* __restrict__ targets,
                          const int* __restrict__ idx,
                          float* __restrict__ out,
                          int n) {
    __shared__ int   s_t[MAX_N];
    __shared__ float s_loss[ROWS_PER_BLOCK];

    const int tid = threadIdx.x;
    const int wid = tid >> 5;
    const int lid = tid & 31;

    // Stage targets once per block (32 KB, L2-hit after first wave touches it).
    #pragma unroll 8
    for (int j = tid; j < n; j += BLOCK) s_t[j] = targets[j];
    __syncthreads();

    const int row = blockIdx.x * ROWS_PER_BLOCK + wid;
    const int my_t = s_t[row];
    const int self_col = idx[row];
    const float* __restrict__ rp = sim + (size_t)self_col * (size_t)n;

    float pos =  FLT_MAX;
    float neg = -FLT_MAX;

    // Warp streams its 32 KB row; unroll 8 -> 8 independent LDG.128 in flight.
    #pragma unroll 8
    for (int it = 0; it < n / (32 * 4); it++) {
        const int j = it * 128 + lid * 4;
        const float4 v = __ldcs(reinterpret_cast<const float4*>(rp + j));
        const int4   t = *reinterpret_cast<const int4*>(&s_t[j]);

        if (t.x == my_t) { if (j + 0 != self_col) pos = fminf(pos, v.x); }
        else             { neg = fmaxf(neg, v.x); }
        if (t.y == my_t) { if (j + 1 != self_col) pos = fminf(pos, v.y); }
        else             { neg = fmaxf(neg, v.y); }
        if (t.z == my_t) { if (j + 2 != self_col) pos = fminf(pos, v.z); }
        else             { neg = fmaxf(neg, v.z); }
        if (t.w == my_t) { if (j + 3 != self_col) pos = fminf(pos, v.w); }
        else             { neg = fmaxf(neg, v.w); }
    }

    // Warp reduction (no block barrier in the hot path).
    #pragma unroll
    for (int off = 16; off > 0; off >>= 1) {
        pos = fminf(pos, __shfl_xor_sync(0xFFFFFFFFu, pos, off));
        neg = fmaxf(neg, __shfl_xor_sync(0xFFFFFFFFu, neg, off));
    }
    if (lid == 0) s_loss[wid] = fmaxf(neg - pos + 0.1f, 0.0f);
    __syncthreads();

    // One thread sums the block's 8 losses in FIXED order -> deterministic.
    __shared__ unsigned int s_is_last;
    if (tid == 0) {
        float bs = 0.0f;
        #pragma unroll
        for (int w = 0; w < ROWS_PER_BLOCK; w++) bs += s_loss[w];
        g_block_sum[blockIdx.x] = bs;
        __threadfence();
        // atomicInc wraps to 0 at GRID-1: counter self-resets every pass.
        unsigned int prev = atomicInc(&g_done_count, GRID - 1);
        s_is_last = (prev == GRID - 1) ? 1u : 0u;
    }
    __syncthreads();

    // Last block reduces the 1024 partials in fixed tree order (deterministic).
    if (s_is_last) {
        __shared__ float s_sum[BLOCK / 32];
        // 1024 floats = 256 float4, one per thread. __ldcg: bypass stale L1.
        const float4* bp = reinterpret_cast<const float4*>(g_block_sum);
        float4 a = __ldcg(bp + tid);
        float acc = (a.x + a.y) + (a.z + a.w);
        #pragma unroll
        for (int off = 16; off > 0; off >>= 1)
            acc += __shfl_xor_sync(0xFFFFFFFFu, acc, off);
        if (lid == 0) s_sum[wid] = acc;
        __syncthreads();
        if (wid == 0) {
            acc = (lid < BLOCK / 32) ? s_sum[lid] : 0.0f;
            #pragma unroll
            for (int off = 4; off > 0; off >>= 1)
                acc += __shfl_xor_sync(0xFFFFFFFFu, acc, off);
            if (lid == 0) out[0] = acc / (float)n;
        }
    }
}

extern "C" void kernel_launch(void* const* d_in, const int* in_sizes, int n_in,
                              void* d_out, int out_size) {
    const float* sim     = (const float*)d_in[0];
    const int*   targets = (const int*)d_in[1];
    const int*   idx     = (const int*)d_in[2];
    float* out = (float*)d_out;

    const int n = in_sizes[1];   // 8192

    triplet_fused_kernel<<<GRID, BLOCK>>>(sim, targets, idx, out, n);
}

// round 5
// speedup vs baseline: 1.2590x; 1.2590x over previous
#include <cuda_runtime.h>
#include <cuda_bf16.h>
#include <float.h>

#define MAX_N 8192
#define BLOCK 256
#define ROWS_PER_BLOCK 8   // one row per warp
#define GRID (MAX_N / ROWS_PER_BLOCK)   // 1024

__device__ float        g_block_sum[GRID];
__device__ unsigned int g_done_count = 0;   // self-resets via atomicInc wrap

__global__ __launch_bounds__(BLOCK, 7)   // regs<=36 -> 7 blocks/SM -> single wave
void triplet_fused_kernel(const float* __restrict__ sim,
                          const int* __restrict__ targets,
                          const int* __restrict__ idx,
                          float* __restrict__ out,
                          int n) {
    __shared__ float s_loss[ROWS_PER_BLOCK];
    __shared__ unsigned int s_is_last;

    const int tid = threadIdx.x;
    const int wid = tid >> 5;
    const int lid = tid & 31;

    const int row = blockIdx.x * ROWS_PER_BLOCK + wid;
    const int my_t = targets[row];
    const int self_col = idx[row];
    const float* __restrict__ rp = sim + (size_t)self_col * (size_t)n;
    const int4* __restrict__ tp = reinterpret_cast<const int4*>(targets);

    float pos =  FLT_MAX;
    float neg = -FLT_MAX;

    // Warp streams its 32 KB row (evict-first) + targets (L1-resident, 32 KB/SM).
    // Unroll 4 -> 4 independent LDG.128 pairs in flight per thread.
    #pragma unroll 4
    for (int it = 0; it < n / (32 * 4); it++) {
        const int j = it * 128 + lid * 4;
        const float4 v = __ldcs(reinterpret_cast<const float4*>(rp + j));
        const int4   t = tp[j >> 2];

        if (t.x == my_t) { if (j + 0 != self_col) pos = fminf(pos, v.x); }
        else             { neg = fmaxf(neg, v.x); }
        if (t.y == my_t) { if (j + 1 != self_col) pos = fminf(pos, v.y); }
        else             { neg = fmaxf(neg, v.y); }
        if (t.z == my_t) { if (j + 2 != self_col) pos = fminf(pos, v.z); }
        else             { neg = fmaxf(neg, v.z); }
        if (t.w == my_t) { if (j + 3 != self_col) pos = fminf(pos, v.w); }
        else             { neg = fmaxf(neg, v.w); }
    }

    // Warp reduction.
    #pragma unroll
    for (int off = 16; off > 0; off >>= 1) {
        pos = fminf(pos, __shfl_xor_sync(0xFFFFFFFFu, pos, off));
        neg = fmaxf(neg, __shfl_xor_sync(0xFFFFFFFFu, neg, off));
    }
    if (lid == 0) s_loss[wid] = fmaxf(neg - pos + 0.1f, 0.0f);
    __syncthreads();

    // One thread sums the block's 8 losses in FIXED order -> deterministic.
    if (tid == 0) {
        float bs = 0.0f;
        #pragma unroll
        for (int w = 0; w < ROWS_PER_BLOCK; w++) bs += s_loss[w];
        g_block_sum[blockIdx.x] = bs;
        __threadfence();
        unsigned int prev = atomicInc(&g_done_count, GRID - 1);
        s_is_last = (prev == GRID - 1) ? 1u : 0u;
    }
    __syncthreads();

    // Last block reduces the 1024 partials in fixed tree order (deterministic).
    if (s_is_last) {
        __shared__ float s_sum[BLOCK / 32];
        const float4* bp = reinterpret_cast<const float4*>(g_block_sum);
        float4 a = __ldcg(bp + tid);
        float acc = (a.x + a.y) + (a.z + a.w);
        #pragma unroll
        for (int off = 16; off > 0; off >>= 1)
            acc += __shfl_xor_sync(0xFFFFFFFFu, acc, off);
        if (lid == 0) s_sum[wid] = acc;
        __syncthreads();
        if (wid == 0) {
            acc = (lid < BLOCK / 32) ? s_sum[lid] : 0.0f;
            #pragma unroll
            for (int off = 4; off > 0; off >>= 1)
                acc += __shfl_xor_sync(0xFFFFFFFFu, acc, off);
            if (lid == 0) out[0] = acc / (float)n;
        }
    }
}

extern "C" void kernel_launch(void* const* d_in, const int* in_sizes, int n_in,
                              void* d_out, int out_size) {
    const float* sim     = (const float*)d_in[0];
    const int*   targets = (const int*)d_in[1];
    const int*   idx     = (const int*)d_in[2];
    float* out = (float*)d_out;

    const int n = in_sizes[1];   // 8192

    triplet_fused_kernel<<<GRID, BLOCK>>>(sim, targets, idx, out, n);
}